// round 1
// baseline (speedup 1.0000x reference)
#include <cuda_runtime.h>
#include <cstdint>

// Problem constants (from reference)
#define N_DENSE    64
#define N_SAMPLES  121
#define N_CHANNELS 384
#define BATCH      2048
#define ROW_IN     (N_DENSE * (1 + N_SAMPLES))   // 7808 floats per input row
#define ROW_OUT    (N_CHANNELS * N_SAMPLES)      // 46464 floats per output batch

// One CTA per batch element. Gather formulation:
//   out[b][c][s] = sum over dense slots d with idx[b][d]==c of data[b][d][s]
// Inverted index built in shared memory as per-channel linked lists.
__global__ __launch_bounds__(512, 4)
void sparse_input_gather_kernel(const float* __restrict__ in,
                                float* __restrict__ out)
{
    __shared__ int head[N_CHANNELS];   // head of slot-chain per channel (-1 = empty)
    __shared__ int nxt[N_DENSE];       // next slot in chain

    const int b = blockIdx.x;
    const int t = threadIdx.x;

    const float* __restrict__ row  = in + (size_t)b * ROW_IN;
    const float* __restrict__ data = row + N_DENSE;
    float* __restrict__ orow = out + (size_t)b * ROW_OUT;

    // ---- build inverted index ----
    if (t < N_CHANNELS) head[t] = -1;
    __syncthreads();
    if (t < N_DENSE) {
        int c = (int)row[t];                    // channel index stored as float
        // defensive clamp (indices are in [0, N_CHANNELS) by construction)
        c = max(0, min(N_CHANNELS - 1, c));
        nxt[t] = atomicExch(&head[c], t);
    }
    __syncthreads();

    // ---- gather: 128 threads (4 warps) per channel row, 4 rows in flight ----
    const int s  = t & 127;        // sample lane (warp-contiguous)
    const int c0 = t >> 7;         // 0..3: which channel of the group

    if (s < N_SAMPLES) {
        #pragma unroll 4
        for (int c = c0; c < N_CHANNELS; c += 4) {
            float acc = 0.0f;
            int d = head[c];                      // warp-uniform
            while (d >= 0) {                      // no divergence: c uniform per warp
                acc += __ldg(&data[d * N_SAMPLES + s]);
                d = nxt[d];
            }
            orow[c * N_SAMPLES + s] = acc;        // coalesced 32-bit stores
        }
    }
}

extern "C" void kernel_launch(void* const* d_in, const int* in_sizes, int n_in,
                              void* d_out, int out_size)
{
    const float* in  = (const float*)d_in[0];
    float*       out = (float*)d_out;
    sparse_input_gather_kernel<<<BATCH, 512>>>(in, out);
}

// round 2
// speedup vs baseline: 1.3661x; 1.3661x over previous
#include <cuda_runtime.h>
#include <cstdint>

#define N_DENSE    64
#define N_SAMPLES  121
#define N_CHANNELS 384
#define BATCH      2048
#define ROW_IN     (N_DENSE * (1 + N_SAMPLES))   // 7808 floats per input row
#define ROW_OUT    (N_CHANNELS * N_SAMPLES)      // 46464 floats per output batch
#define N_VEC      (ROW_OUT / 4)                 // 11616 float4 per batch row
#define NTHREADS   512

// One CTA per batch element. Gather formulation with shared-memory inverted
// index (per-channel linked lists), float4 output stores over the flat row.
__global__ __launch_bounds__(NTHREADS)
void sparse_input_gather_v2(const float* __restrict__ in,
                            float* __restrict__ out)
{
    __shared__ int head[N_CHANNELS];   // head of slot-chain per channel (-1 = empty)
    __shared__ int nxt[N_DENSE];       // next slot in chain

    const int b = blockIdx.x;
    const int t = threadIdx.x;

    const float* __restrict__ row  = in + (size_t)b * ROW_IN;
    const float* __restrict__ data = row + N_DENSE;
    float4* __restrict__ ovec = reinterpret_cast<float4*>(out + (size_t)b * ROW_OUT);

    // ---- build inverted index ----
    if (t < N_CHANNELS) head[t] = -1;
    __syncthreads();
    if (t < N_DENSE) {
        int c = (int)row[t];
        c = max(0, min(N_CHANNELS - 1, c));
        nxt[t] = atomicExch(&head[c], t);
    }
    __syncthreads();

    // ---- gather, one float4 of the flat output row per iteration ----
    #pragma unroll 4
    for (int v = t; v < N_VEC; v += NTHREADS) {
        const int p = v << 2;                 // flat element index
        const int c = p / N_SAMPLES;          // compiler emits mul-hi magic
        const int s = p - c * N_SAMPLES;

        float4 acc = make_float4(0.f, 0.f, 0.f, 0.f);

        if (s <= N_SAMPLES - 4) {
            // fast path: all 4 elements in the same channel row
            int d = head[c];
            while (d >= 0) {
                const float* g = data + d * N_SAMPLES + s;
                acc.x += __ldg(g + 0);
                acc.y += __ldg(g + 1);
                acc.z += __ldg(g + 2);
                acc.w += __ldg(g + 3);
                d = nxt[d];
            }
        } else {
            // slow path (~3.3% of vectors): float4 straddles a channel boundary
            float* a = reinterpret_cast<float*>(&acc);
            #pragma unroll
            for (int j = 0; j < 4; j++) {
                const int pj = p + j;
                const int cj = pj / N_SAMPLES;
                const int sj = pj - cj * N_SAMPLES;
                int d = head[cj];
                while (d >= 0) {
                    a[j] += __ldg(data + d * N_SAMPLES + sj);
                    d = nxt[d];
                }
            }
        }
        ovec[v] = acc;                        // coalesced 128-bit stores
    }
}

extern "C" void kernel_launch(void* const* d_in, const int* in_sizes, int n_in,
                              void* d_out, int out_size)
{
    const float* in  = (const float*)d_in[0];
    float*       out = (float*)d_out;
    sparse_input_gather_v2<<<BATCH, NTHREADS>>>(in, out);
}

// round 3
// speedup vs baseline: 1.6341x; 1.1961x over previous
#include <cuda_runtime.h>
#include <cstdint>

#define N_DENSE    64
#define N_SAMPLES  121
#define N_CHANNELS 384
#define BATCH      2048
#define ROW_IN     (N_DENSE * (1 + N_SAMPLES))   // 7808 floats per input row
#define ROW_OUT    (N_CHANNELS * N_SAMPLES)      // 46464 floats per output batch
#define N_VEC      (ROW_OUT / 4)                 // 11616 float4 per batch row
#define DATA_F     (N_DENSE * N_SAMPLES)         // 7744 floats of sample data
#define NTHREADS   512

// One CTA per batch element.
//  Phase 1: stream the 31KB data tile into SMEM (float4), build inverted index.
//  Phase 2: gather with chain walks reading SMEM (29cyc LDS instead of ~577cyc
//           DRAM LDG), float4 streaming stores over the flat output row,
//           incremental (c,s) tracking (no per-iteration division).
__global__ __launch_bounds__(NTHREADS)
void sparse_input_gather_v3(const float* __restrict__ in,
                            float* __restrict__ out)
{
    __shared__ float sdata[DATA_F];    // staged sample data [64][121]
    __shared__ int   head[N_CHANNELS]; // chain head per channel (-1 = empty)
    __shared__ int   nxt[N_DENSE];     // next slot in chain

    const int b = blockIdx.x;
    const int t = threadIdx.x;

    const float* __restrict__ row  = in + (size_t)b * ROW_IN;
    const float* __restrict__ data = row + N_DENSE;

    // ---- phase 1: stage data + build inverted index ----
    // hoist the index load so its latency overlaps the copy
    int my_c = -1;
    if (t < N_DENSE) {
        int c = (int)__ldg(&row[t]);
        my_c = max(0, min(N_CHANNELS - 1, c));
    }
    if (t < N_CHANNELS) head[t] = -1;

    // data row is 16B-aligned: b*7808 + 64, both multiples of 4 floats
    {
        const float4* __restrict__ src = reinterpret_cast<const float4*>(data);
        float4* __restrict__ dst = reinterpret_cast<float4*>(sdata);
        #pragma unroll
        for (int i = t; i < DATA_F / 4; i += NTHREADS)   // 1936 vec4
            dst[i] = src[i];
    }
    __syncthreads();

    if (t < N_DENSE)
        nxt[t] = atomicExch(&head[my_c], t);
    __syncthreads();

    // ---- phase 2: gather ----
    float4* __restrict__ ovec = reinterpret_cast<float4*>(out + (size_t)b * ROW_OUT);

    // initial (c, s) for p = 4t; thereafter p += 2048 each iteration:
    // 2048 = 16*121 + 112  ->  c += 16, s += 112, wrap
    int c = (4 * t) / N_SAMPLES;
    int s = 4 * t - c * N_SAMPLES;

    #pragma unroll 4
    for (int v = t; v < N_VEC; v += NTHREADS) {
        float4 acc = make_float4(0.f, 0.f, 0.f, 0.f);

        if (s <= N_SAMPLES - 4) {
            // fast path: all 4 samples in channel c
            int d = head[c];
            while (d >= 0) {
                const float* g = sdata + d * N_SAMPLES + s;
                acc.x += g[0];
                acc.y += g[1];
                acc.z += g[2];
                acc.w += g[3];
                d = nxt[d];
            }
        } else {
            // boundary vector (~3.3%): samples split across channels c, c+1
            float* a = reinterpret_cast<float*>(&acc);
            #pragma unroll
            for (int j = 0; j < 4; j++) {
                int sj = s + j, cj = c;
                if (sj >= N_SAMPLES) { sj -= N_SAMPLES; cj++; }
                int d = head[cj];
                while (d >= 0) {
                    a[j] += sdata[d * N_SAMPLES + sj];
                    d = nxt[d];
                }
            }
        }
        __stcs(&ovec[v], acc);        // streaming 128-bit store, write-once data

        // advance (c, s) by 2048 flat elements
        s += 112; c += 16;
        if (s >= N_SAMPLES) { s -= N_SAMPLES; c++; }
    }
}

extern "C" void kernel_launch(void* const* d_in, const int* in_sizes, int n_in,
                              void* d_out, int out_size)
{
    const float* in  = (const float*)d_in[0];
    float*       out = (float*)d_out;
    sparse_input_gather_v3<<<BATCH, NTHREADS>>>(in, out);
}